// round 1
// baseline (speedup 1.0000x reference)
#include <cuda_runtime.h>
#include <cuda_bf16.h>

// ---------------------------------------------------------------------------
// PhysicsConvolution: X0 = notes@w ; X1 = segment_sum(ew * X0[dst], src) ;
// out = concat(relu(X1 + b), X0[garment:])
//
// Scratch (allocation-free rule): __device__ globals. N*H = 12.8M floats.
// ---------------------------------------------------------------------------

#define HD 128            // hidden dim H (and D); asserted by shapes in this problem
#define BM 64             // GEMM row tile

__device__ float4 g_X0[3400000];   // >= N*H/4 = 3.2M float4  (54.4 MB)
__device__ float4 g_X1[3400000];

// ---------------------------------------------------------------------------
// GEMM: X0 = A[N,128] @ W[128,128].  Also zeroes X1 rows and writes the
// out-tail rows (X0[g:]) directly.
// Mapping: 256 threads, tx = lane (32 col-float4s), ty = warp (8 row groups),
// each thread computes an 8-row x 4-col micro-tile (32 accumulators).
// ---------------------------------------------------------------------------
__global__ __launch_bounds__(256) void gemm_kernel(
    const float4* __restrict__ A4,   // notes as float4
    const float4* __restrict__ W4,   // w as float4
    float4* __restrict__ out4,       // d_out as float4
    int N, int g)
{
    __shared__ float4 sA[BM * 32];     // 64 rows x 32 f4 along K
    __shared__ float4 sB[HD * 32];     // 128 k-rows x 32 col-f4

    const int tid  = threadIdx.x;
    const int row0 = blockIdx.x * BM;

    // Load W (64KB) — L2-resident after first block
    #pragma unroll
    for (int i = tid; i < HD * 32; i += 256) sB[i] = W4[i];

    // Load A tile (guarded)
    for (int i = tid; i < BM * 32; i += 256) {
        int r = row0 + (i >> 5);
        sA[i] = (r < N) ? A4[(size_t)r * 32 + (i & 31)]
                        : make_float4(0.f, 0.f, 0.f, 0.f);
    }
    __syncthreads();

    const int tx = tid & 31;   // col-f4 index: cols 4*tx .. 4*tx+3
    const int ty = tid >> 5;   // row group: rows ty*8 .. ty*8+7

    float4 acc[8];
    #pragma unroll
    for (int i = 0; i < 8; i++) acc[i] = make_float4(0.f, 0.f, 0.f, 0.f);

    #pragma unroll 4
    for (int k4 = 0; k4 < 32; k4++) {
        // 4 consecutive k values; B rows are conflict-free LDS.128,
        // A loads are warp-broadcast (same address across lanes).
        float4 b0 = sB[(k4 * 4 + 0) * 32 + tx];
        float4 b1 = sB[(k4 * 4 + 1) * 32 + tx];
        float4 b2 = sB[(k4 * 4 + 2) * 32 + tx];
        float4 b3 = sB[(k4 * 4 + 3) * 32 + tx];
        #pragma unroll
        for (int i = 0; i < 8; i++) {
            float4 a = sA[(ty * 8 + i) * 32 + k4];
            acc[i].x += a.x * b0.x + a.y * b1.x + a.z * b2.x + a.w * b3.x;
            acc[i].y += a.x * b0.y + a.y * b1.y + a.z * b2.y + a.w * b3.y;
            acc[i].z += a.x * b0.z + a.y * b1.z + a.z * b2.z + a.w * b3.z;
            acc[i].w += a.x * b0.w + a.y * b1.w + a.z * b2.w + a.w * b3.w;
        }
    }

    const float4 z4 = make_float4(0.f, 0.f, 0.f, 0.f);
    #pragma unroll
    for (int i = 0; i < 8; i++) {
        int r = row0 + ty * 8 + i;
        if (r < N) {
            g_X0[(size_t)r * 32 + tx] = acc[i];
            g_X1[(size_t)r * 32 + tx] = z4;          // zero-init for atomics
            if (r >= g)                               // out tail = X0[g:]
                out4[(size_t)(N + r - g) * 32 + tx] = acc[i];
        }
    }
}

// ---------------------------------------------------------------------------
// Edge scatter: one warp per edge (4 edges unrolled per warp for gather MLP).
// lane covers one float4 of the 128-wide row.  float4 atomicAdd (sm_90+).
// ---------------------------------------------------------------------------
__global__ __launch_bounds__(256) void edge_kernel(
    const int*   __restrict__ esrc,
    const int*   __restrict__ edst,
    const float* __restrict__ ew,
    int E)
{
    const int lane  = threadIdx.x & 31;
    const int warp  = (blockIdx.x * blockDim.x + threadIdx.x) >> 5;
    const int e0    = warp * 4;
    if (e0 >= E) return;
    const int n = min(4, E - e0);

    int    s[4];
    float  w[4];
    float4 v[4];

    #pragma unroll
    for (int u = 0; u < 4; u++) {
        if (u < n) {
            int e = e0 + u;
            int d = __ldg(edst + e);
            s[u]  = __ldg(esrc + e);
            w[u]  = __ldg(ew + e);
            v[u]  = g_X0[(size_t)d * 32 + lane];      // L2-resident gather
        }
    }
    #pragma unroll
    for (int u = 0; u < 4; u++) {
        if (u < n) {
            float4 t = make_float4(v[u].x * w[u], v[u].y * w[u],
                                   v[u].z * w[u], v[u].w * w[u]);
            atomicAdd(&g_X1[(size_t)s[u] * 32 + lane], t);  // RED.128
        }
    }
}

// ---------------------------------------------------------------------------
// Epilogue: out[0:N] = relu(X1 + b)
// ---------------------------------------------------------------------------
__global__ __launch_bounds__(256) void relu_kernel(
    const float4* __restrict__ b4,
    float4* __restrict__ out4,
    int total4)
{
    int i = blockIdx.x * blockDim.x + threadIdx.x;
    if (i >= total4) return;
    float4 bb = __ldg(b4 + (i & 31));
    float4 x  = g_X1[i];
    x.x = fmaxf(x.x + bb.x, 0.f);
    x.y = fmaxf(x.y + bb.y, 0.f);
    x.z = fmaxf(x.z + bb.z, 0.f);
    x.w = fmaxf(x.w + bb.w, 0.f);
    out4[i] = x;
}

// ---------------------------------------------------------------------------
extern "C" void kernel_launch(void* const* d_in, const int* in_sizes, int n_in,
                              void* d_out, int out_size)
{
    const float* notes = (const float*)d_in[0];
    const float* w     = (const float*)d_in[1];
    const float* b     = (const float*)d_in[2];
    const int*   esrc  = (const int*)  d_in[3];
    const int*   edst  = (const int*)  d_in[4];
    const float* ew    = (const float*)d_in[5];

    const int H = in_sizes[2];            // 128
    const int D = in_sizes[1] / H;        // 128
    const int N = in_sizes[0] / D;        // 100000
    const int E = in_sizes[3];            // 1600000
    const int g = 2 * N - out_size / H;   // garment_size (80000)

    float4* out4 = (float4*)d_out;

    // 1) GEMM + zero X1 + out-tail write
    gemm_kernel<<<(N + BM - 1) / BM, 256>>>(
        (const float4*)notes, (const float4*)w, out4, N, g);

    // 2) Edge scatter: 4 edges/warp, 8 warps/block -> 32 edges/block
    edge_kernel<<<(E + 31) / 32, 256>>>(esrc, edst, ew, E);

    // 3) relu(X1 + b) -> out head
    relu_kernel<<<(N * (H / 4) + 255) / 256, 256>>>(
        (const float4*)b, out4, N * (H / 4));
}

// round 2
// speedup vs baseline: 1.2889x; 1.2889x over previous
#include <cuda_runtime.h>
#include <cuda_bf16.h>

// ---------------------------------------------------------------------------
// PhysicsConvolution: X0 = notes@w ; X1 = segment_sum(ew * X0[dst], src) ;
// out = concat(relu(X1 + b), X0[garment:])
//
// Edge phase: per-call CSR build (hist -> scan -> scatter) then a
// register-accumulating gather (warp per node) that fuses bias+relu.
// No RED atomics on the 128-wide rows at all.
// ---------------------------------------------------------------------------

#define HD 128            // hidden dim H (and D)
#define BM 64             // GEMM row tile

#define MAXN 131072       // node capacity (N=100000)
#define MAXE 1700000      // edge capacity (E=1600000)
#define SCAN_BLK 1024     // elements per scan block
#define MAXNB (MAXN / SCAN_BLK)   // 128 scan blocks max

__device__ float4 g_X0[3400000];        // >= N*H/4 float4 (54.4 MB)
__device__ int    g_sdst[MAXE];         // CSR: dst sorted by src
__device__ float  g_sw[MAXE];           // CSR: weight sorted by src
__device__ int    g_cnt[MAXN + 1];      // per-src degree
__device__ int    g_off[MAXN + 2];      // exclusive offsets
__device__ int    g_cur[MAXN + 1];      // scatter cursors
__device__ int    g_blk[256];           // scan block totals
__device__ int    g_blko[256];          // scan block offsets

// ---------------------------------------------------------------------------
// GEMM: X0 = A[N,128] @ W[128,128]; writes out-tail rows (X0[g:]) directly.
// ---------------------------------------------------------------------------
__global__ __launch_bounds__(256) void gemm_kernel(
    const float4* __restrict__ A4,
    const float4* __restrict__ W4,
    float4* __restrict__ out4,
    int N, int g)
{
    __shared__ float4 sA[BM * 32];
    __shared__ float4 sB[HD * 32];

    const int tid  = threadIdx.x;
    const int row0 = blockIdx.x * BM;

    #pragma unroll
    for (int i = tid; i < HD * 32; i += 256) sB[i] = W4[i];
    for (int i = tid; i < BM * 32; i += 256) {
        int r = row0 + (i >> 5);
        sA[i] = (r < N) ? A4[(size_t)r * 32 + (i & 31)]
                        : make_float4(0.f, 0.f, 0.f, 0.f);
    }
    __syncthreads();

    const int tx = tid & 31;
    const int ty = tid >> 5;

    float4 acc[8];
    #pragma unroll
    for (int i = 0; i < 8; i++) acc[i] = make_float4(0.f, 0.f, 0.f, 0.f);

    #pragma unroll 4
    for (int k4 = 0; k4 < 32; k4++) {
        float4 b0 = sB[(k4 * 4 + 0) * 32 + tx];
        float4 b1 = sB[(k4 * 4 + 1) * 32 + tx];
        float4 b2 = sB[(k4 * 4 + 2) * 32 + tx];
        float4 b3 = sB[(k4 * 4 + 3) * 32 + tx];
        #pragma unroll
        for (int i = 0; i < 8; i++) {
            float4 a = sA[(ty * 8 + i) * 32 + k4];
            acc[i].x += a.x * b0.x + a.y * b1.x + a.z * b2.x + a.w * b3.x;
            acc[i].y += a.x * b0.y + a.y * b1.y + a.z * b2.y + a.w * b3.y;
            acc[i].z += a.x * b0.z + a.y * b1.z + a.z * b2.z + a.w * b3.z;
            acc[i].w += a.x * b0.w + a.y * b1.w + a.z * b2.w + a.w * b3.w;
        }
    }

    #pragma unroll
    for (int i = 0; i < 8; i++) {
        int r = row0 + ty * 8 + i;
        if (r < N) {
            g_X0[(size_t)r * 32 + tx] = acc[i];
            if (r >= g)
                out4[(size_t)(N + r - g) * 32 + tx] = acc[i];
        }
    }
}

// ---------------------------------------------------------------------------
// CSR build
// ---------------------------------------------------------------------------
__global__ void zero_cnt_kernel(int N) {
    for (int i = blockIdx.x * blockDim.x + threadIdx.x; i < N;
         i += gridDim.x * blockDim.x)
        g_cnt[i] = 0;
}

__global__ void hist_kernel(const int* __restrict__ esrc, int E) {
    for (int e = blockIdx.x * blockDim.x + threadIdx.x; e < E;
         e += gridDim.x * blockDim.x)
        atomicAdd(&g_cnt[esrc[e]], 1);
}

// scan phase 1: each block scans 1024 counts, writes local-exclusive offsets
// plus its block total.
__global__ __launch_bounds__(256) void scan1_kernel(int N) {
    __shared__ int ssum[256];
    const int t = threadIdx.x;
    const int base = blockIdx.x * SCAN_BLK + t * 4;

    int c0 = (base + 0 < N) ? g_cnt[base + 0] : 0;
    int c1 = (base + 1 < N) ? g_cnt[base + 1] : 0;
    int c2 = (base + 2 < N) ? g_cnt[base + 2] : 0;
    int c3 = (base + 3 < N) ? g_cnt[base + 3] : 0;
    int tot = c0 + c1 + c2 + c3;

    ssum[t] = tot;
    __syncthreads();
    #pragma unroll
    for (int off = 1; off < 256; off <<= 1) {
        int v = (t >= off) ? ssum[t - off] : 0;
        __syncthreads();
        ssum[t] += v;
        __syncthreads();
    }
    int ex = ssum[t] - tot;   // exclusive prefix of this thread within block

    if (base + 0 < N) g_off[base + 0] = ex;
    if (base + 1 < N) g_off[base + 1] = ex + c0;
    if (base + 2 < N) g_off[base + 2] = ex + c0 + c1;
    if (base + 3 < N) g_off[base + 3] = ex + c0 + c1 + c2;
    if (t == 255) g_blk[blockIdx.x] = ssum[255];
}

// scan phase 2: single block exclusive-scans block totals.
__global__ __launch_bounds__(256) void scan2_kernel(int NB) {
    __shared__ int ssum[256];
    const int t = threadIdx.x;
    int v0 = (t < NB) ? g_blk[t] : 0;
    ssum[t] = v0;
    __syncthreads();
    #pragma unroll
    for (int off = 1; off < 256; off <<= 1) {
        int v = (t >= off) ? ssum[t - off] : 0;
        __syncthreads();
        ssum[t] += v;
        __syncthreads();
    }
    if (t < NB) g_blko[t] = ssum[t] - v0;
}

// scan phase 3: add block offsets, init cursors, set sentinel.
__global__ void scan3_kernel(int N, int E) {
    int i = blockIdx.x * blockDim.x + threadIdx.x;
    if (i < N) {
        int v = g_off[i] + g_blko[i / SCAN_BLK];
        g_off[i] = v;
        g_cur[i] = v;
    }
    if (i == 0) g_off[N] = E;
}

__global__ void scatter_kernel(const int* __restrict__ esrc,
                               const int* __restrict__ edst,
                               const float* __restrict__ ew, int E) {
    for (int e = blockIdx.x * blockDim.x + threadIdx.x; e < E;
         e += gridDim.x * blockDim.x) {
        int s = esrc[e];
        int p = atomicAdd(&g_cur[s], 1);
        g_sdst[p] = edst[e];
        g_sw[p]   = ew[e];
    }
}

// ---------------------------------------------------------------------------
// Gather: one warp per node. acc in registers, fused bias+relu -> out head.
// ---------------------------------------------------------------------------
__global__ __launch_bounds__(256) void gather_kernel(
    const float4* __restrict__ b4,
    float4* __restrict__ out4,
    int N)
{
    const int lane = threadIdx.x & 31;
    const int node = (blockIdx.x * blockDim.x + threadIdx.x) >> 5;
    if (node >= N) return;

    const int start = g_off[node];
    const int end   = g_off[node + 1];

    float4 acc = make_float4(0.f, 0.f, 0.f, 0.f);

    for (int j = start; j < end; j += 32) {
        const int m = min(32, end - j);
        int   dv = 0;
        float wv = 0.f;
        if (lane < m) {
            dv = g_sdst[j + lane];
            wv = g_sw[j + lane];
        }
        int k = 0;
        for (; k + 4 <= m; k += 4) {
            int   d0 = __shfl_sync(0xffffffffu, dv, k + 0);
            int   d1 = __shfl_sync(0xffffffffu, dv, k + 1);
            int   d2 = __shfl_sync(0xffffffffu, dv, k + 2);
            int   d3 = __shfl_sync(0xffffffffu, dv, k + 3);
            float w0 = __shfl_sync(0xffffffffu, wv, k + 0);
            float w1 = __shfl_sync(0xffffffffu, wv, k + 1);
            float w2 = __shfl_sync(0xffffffffu, wv, k + 2);
            float w3 = __shfl_sync(0xffffffffu, wv, k + 3);
            float4 v0 = g_X0[(size_t)d0 * 32 + lane];
            float4 v1 = g_X0[(size_t)d1 * 32 + lane];
            float4 v2 = g_X0[(size_t)d2 * 32 + lane];
            float4 v3 = g_X0[(size_t)d3 * 32 + lane];
            acc.x += w0 * v0.x + w1 * v1.x + w2 * v2.x + w3 * v3.x;
            acc.y += w0 * v0.y + w1 * v1.y + w2 * v2.y + w3 * v3.y;
            acc.z += w0 * v0.z + w1 * v1.z + w2 * v2.z + w3 * v3.z;
            acc.w += w0 * v0.w + w1 * v1.w + w2 * v2.w + w3 * v3.w;
        }
        for (; k < m; k++) {
            int   d = __shfl_sync(0xffffffffu, dv, k);
            float w = __shfl_sync(0xffffffffu, wv, k);
            float4 v = g_X0[(size_t)d * 32 + lane];
            acc.x += w * v.x;
            acc.y += w * v.y;
            acc.z += w * v.z;
            acc.w += w * v.w;
        }
    }

    float4 bb = __ldg(b4 + lane);
    acc.x = fmaxf(acc.x + bb.x, 0.f);
    acc.y = fmaxf(acc.y + bb.y, 0.f);
    acc.z = fmaxf(acc.z + bb.z, 0.f);
    acc.w = fmaxf(acc.w + bb.w, 0.f);
    out4[(size_t)node * 32 + lane] = acc;
}

// ---------------------------------------------------------------------------
extern "C" void kernel_launch(void* const* d_in, const int* in_sizes, int n_in,
                              void* d_out, int out_size)
{
    const float* notes = (const float*)d_in[0];
    const float* w     = (const float*)d_in[1];
    const float* b     = (const float*)d_in[2];
    const int*   esrc  = (const int*)  d_in[3];
    const int*   edst  = (const int*)  d_in[4];
    const float* ew    = (const float*)d_in[5];

    const int H = in_sizes[2];            // 128
    const int D = in_sizes[1] / H;        // 128
    const int N = in_sizes[0] / D;        // 100000
    const int E = in_sizes[3];            // 1600000
    const int g = 2 * N - out_size / H;   // garment_size

    float4* out4 = (float4*)d_out;
    const int NB = (N + SCAN_BLK - 1) / SCAN_BLK;

    // CSR build (independent of GEMM)
    zero_cnt_kernel<<<(N + 255) / 256, 256>>>(N);
    hist_kernel<<<592, 256>>>(esrc, E);
    scan1_kernel<<<NB, 256>>>(N);
    scan2_kernel<<<1, 256>>>(NB);
    scan3_kernel<<<(N + 255) / 256, 256>>>(N, E);
    scatter_kernel<<<592, 256>>>(esrc, edst, ew, E);

    // GEMM + out-tail write
    gemm_kernel<<<(N + BM - 1) / BM, 256>>>(
        (const float4*)notes, (const float4*)w, out4, N, g);

    // Gather + bias + relu -> out head
    gather_kernel<<<(N * 32 + 255) / 256, 256>>>(
        (const float4*)b, out4, N);
}

// round 3
// speedup vs baseline: 1.3810x; 1.0714x over previous
#include <cuda_runtime.h>
#include <cuda_fp16.h>
#include <cuda_bf16.h>

// ---------------------------------------------------------------------------
// PhysicsConvolution: X0 = notes@w ; X1 = segment_sum(ew * X0[dst], src) ;
// out = concat(relu(X1 + b), X0[garment:])
//
// X0 kept ONLY as fp16 (gather is its sole consumer; out-tail is written
// from GEMM accumulators in fp32). CSR build -> register gather, no atomics
// on wide rows. g_cnt zero-invariant maintained by scan1 (no zero kernel).
// ---------------------------------------------------------------------------

#define HD 128
#define BM 64

#define MAXN 131072
#define MAXE 1700000
#define SCAN_BLK 1024

__device__ uint2 g_X0h[3400000];        // fp16 X0: [N][32] uint2 = 4 halves each
__device__ int2  g_sdw[MAXE];           // CSR payload: {dst, w as int}
__device__ int   g_cnt[MAXN + 1];       // zero at load; scan1 restores zeros
__device__ int   g_off[MAXN + 2];
__device__ int   g_cur[MAXN + 1];
__device__ int   g_blk[256];
__device__ int   g_blko[256];

// ---------------------------------------------------------------------------
// GEMM: X0 = A[N,128] @ W[128,128]; stores X0 as fp16, out-tail as fp32.
// ---------------------------------------------------------------------------
__global__ __launch_bounds__(256) void gemm_kernel(
    const float4* __restrict__ A4,
    const float4* __restrict__ W4,
    float4* __restrict__ out4,
    int N, int g)
{
    __shared__ float4 sA[BM * 32];
    __shared__ float4 sB[HD * 32];

    const int tid  = threadIdx.x;
    const int row0 = blockIdx.x * BM;

    #pragma unroll
    for (int i = tid; i < HD * 32; i += 256) sB[i] = W4[i];
    for (int i = tid; i < BM * 32; i += 256) {
        int r = row0 + (i >> 5);
        sA[i] = (r < N) ? A4[(size_t)r * 32 + (i & 31)]
                        : make_float4(0.f, 0.f, 0.f, 0.f);
    }
    __syncthreads();

    const int tx = tid & 31;
    const int ty = tid >> 5;

    float4 acc[8];
    #pragma unroll
    for (int i = 0; i < 8; i++) acc[i] = make_float4(0.f, 0.f, 0.f, 0.f);

    #pragma unroll 4
    for (int k4 = 0; k4 < 32; k4++) {
        float4 b0 = sB[(k4 * 4 + 0) * 32 + tx];
        float4 b1 = sB[(k4 * 4 + 1) * 32 + tx];
        float4 b2 = sB[(k4 * 4 + 2) * 32 + tx];
        float4 b3 = sB[(k4 * 4 + 3) * 32 + tx];
        #pragma unroll
        for (int i = 0; i < 8; i++) {
            float4 a = sA[(ty * 8 + i) * 32 + k4];
            acc[i].x += a.x * b0.x + a.y * b1.x + a.z * b2.x + a.w * b3.x;
            acc[i].y += a.x * b0.y + a.y * b1.y + a.z * b2.y + a.w * b3.y;
            acc[i].z += a.x * b0.z + a.y * b1.z + a.z * b2.z + a.w * b3.z;
            acc[i].w += a.x * b0.w + a.y * b1.w + a.z * b2.w + a.w * b3.w;
        }
    }

    #pragma unroll
    for (int i = 0; i < 8; i++) {
        int r = row0 + ty * 8 + i;
        if (r < N) {
            __half2 lo = __float22half2_rn(make_float2(acc[i].x, acc[i].y));
            __half2 hi = __float22half2_rn(make_float2(acc[i].z, acc[i].w));
            uint2 p;
            p.x = *reinterpret_cast<unsigned*>(&lo);
            p.y = *reinterpret_cast<unsigned*>(&hi);
            g_X0h[(size_t)r * 32 + tx] = p;
            if (r >= g)
                out4[(size_t)(N + r - g) * 32 + tx] = acc[i];   // exact fp32 tail
        }
    }
}

// ---------------------------------------------------------------------------
// CSR build
// ---------------------------------------------------------------------------
__global__ void hist_kernel(const int* __restrict__ esrc, int E) {
    for (int e = blockIdx.x * blockDim.x + threadIdx.x; e < E;
         e += gridDim.x * blockDim.x)
        atomicAdd(&g_cnt[esrc[e]], 1);
}

// scan1 also re-zeroes g_cnt (restores the launch-time zero invariant).
__global__ __launch_bounds__(256) void scan1_kernel(int N) {
    __shared__ int ssum[256];
    const int t = threadIdx.x;
    const int base = blockIdx.x * SCAN_BLK + t * 4;

    int c0 = 0, c1 = 0, c2 = 0, c3 = 0;
    if (base + 0 < N) { c0 = g_cnt[base + 0]; g_cnt[base + 0] = 0; }
    if (base + 1 < N) { c1 = g_cnt[base + 1]; g_cnt[base + 1] = 0; }
    if (base + 2 < N) { c2 = g_cnt[base + 2]; g_cnt[base + 2] = 0; }
    if (base + 3 < N) { c3 = g_cnt[base + 3]; g_cnt[base + 3] = 0; }
    int tot = c0 + c1 + c2 + c3;

    ssum[t] = tot;
    __syncthreads();
    #pragma unroll
    for (int off = 1; off < 256; off <<= 1) {
        int v = (t >= off) ? ssum[t - off] : 0;
        __syncthreads();
        ssum[t] += v;
        __syncthreads();
    }
    int ex = ssum[t] - tot;

    if (base + 0 < N) g_off[base + 0] = ex;
    if (base + 1 < N) g_off[base + 1] = ex + c0;
    if (base + 2 < N) g_off[base + 2] = ex + c0 + c1;
    if (base + 3 < N) g_off[base + 3] = ex + c0 + c1 + c2;
    if (t == 255) g_blk[blockIdx.x] = ssum[255];
}

__global__ __launch_bounds__(256) void scan2_kernel(int NB) {
    __shared__ int ssum[256];
    const int t = threadIdx.x;
    int v0 = (t < NB) ? g_blk[t] : 0;
    ssum[t] = v0;
    __syncthreads();
    #pragma unroll
    for (int off = 1; off < 256; off <<= 1) {
        int v = (t >= off) ? ssum[t - off] : 0;
        __syncthreads();
        ssum[t] += v;
        __syncthreads();
    }
    if (t < NB) g_blko[t] = ssum[t] - v0;
}

__global__ void scan3_kernel(int N, int E) {
    int i = blockIdx.x * blockDim.x + threadIdx.x;
    if (i < N) {
        int v = g_off[i] + g_blko[i / SCAN_BLK];
        g_off[i] = v;
        g_cur[i] = v;
    }
    if (i == 0) g_off[N] = E;
}

__global__ void scatter_kernel(const int* __restrict__ esrc,
                               const int* __restrict__ edst,
                               const float* __restrict__ ew, int E) {
    for (int e = blockIdx.x * blockDim.x + threadIdx.x; e < E;
         e += gridDim.x * blockDim.x) {
        int s = esrc[e];
        int p = atomicAdd(&g_cur[s], 1);
        g_sdw[p] = make_int2(edst[e], __float_as_int(ew[e]));
    }
}

// ---------------------------------------------------------------------------
// Gather: warp per node; lane covers 4 hidden cols (8B fp16 load per edge).
// fp32 accumulate, fused bias+relu -> out head.
// ---------------------------------------------------------------------------
__global__ __launch_bounds__(256) void gather_kernel(
    const float4* __restrict__ b4,
    float4* __restrict__ out4,
    int N)
{
    const int lane = threadIdx.x & 31;
    const int node = (blockIdx.x * blockDim.x + threadIdx.x) >> 5;
    if (node >= N) return;

    const int start = g_off[node];
    const int end   = g_off[node + 1];

    float4 acc = make_float4(0.f, 0.f, 0.f, 0.f);

    for (int j = start; j < end; j += 32) {
        const int m = min(32, end - j);
        int   dv = 0;
        float wv = 0.f;
        if (lane < m) {
            int2 p = g_sdw[j + lane];
            dv = p.x;
            wv = __int_as_float(p.y);
        }
        int k = 0;
        for (; k + 4 <= m; k += 4) {
            int   d0 = __shfl_sync(0xffffffffu, dv, k + 0);
            int   d1 = __shfl_sync(0xffffffffu, dv, k + 1);
            int   d2 = __shfl_sync(0xffffffffu, dv, k + 2);
            int   d3 = __shfl_sync(0xffffffffu, dv, k + 3);
            float w0 = __shfl_sync(0xffffffffu, wv, k + 0);
            float w1 = __shfl_sync(0xffffffffu, wv, k + 1);
            float w2 = __shfl_sync(0xffffffffu, wv, k + 2);
            float w3 = __shfl_sync(0xffffffffu, wv, k + 3);
            uint2 u0 = g_X0h[(size_t)d0 * 32 + lane];
            uint2 u1 = g_X0h[(size_t)d1 * 32 + lane];
            uint2 u2 = g_X0h[(size_t)d2 * 32 + lane];
            uint2 u3 = g_X0h[(size_t)d3 * 32 + lane];
            float2 a0 = __half22float2(*reinterpret_cast<__half2*>(&u0.x));
            float2 b0 = __half22float2(*reinterpret_cast<__half2*>(&u0.y));
            float2 a1 = __half22float2(*reinterpret_cast<__half2*>(&u1.x));
            float2 b1 = __half22float2(*reinterpret_cast<__half2*>(&u1.y));
            float2 a2 = __half22float2(*reinterpret_cast<__half2*>(&u2.x));
            float2 b2 = __half22float2(*reinterpret_cast<__half2*>(&u2.y));
            float2 a3 = __half22float2(*reinterpret_cast<__half2*>(&u3.x));
            float2 b3 = __half22float2(*reinterpret_cast<__half2*>(&u3.y));
            acc.x += w0 * a0.x + w1 * a1.x + w2 * a2.x + w3 * a3.x;
            acc.y += w0 * a0.y + w1 * a1.y + w2 * a2.y + w3 * a3.y;
            acc.z += w0 * b0.x + w1 * b1.x + w2 * b2.x + w3 * b3.x;
            acc.w += w0 * b0.y + w1 * b1.y + w2 * b2.y + w3 * b3.y;
        }
        for (; k < m; k++) {
            int   d = __shfl_sync(0xffffffffu, dv, k);
            float w = __shfl_sync(0xffffffffu, wv, k);
            uint2 u = g_X0h[(size_t)d * 32 + lane];
            float2 a = __half22float2(*reinterpret_cast<__half2*>(&u.x));
            float2 c = __half22float2(*reinterpret_cast<__half2*>(&u.y));
            acc.x += w * a.x;
            acc.y += w * a.y;
            acc.z += w * c.x;
            acc.w += w * c.y;
        }
    }

    float4 bb = __ldg(b4 + lane);
    acc.x = fmaxf(acc.x + bb.x, 0.f);
    acc.y = fmaxf(acc.y + bb.y, 0.f);
    acc.z = fmaxf(acc.z + bb.z, 0.f);
    acc.w = fmaxf(acc.w + bb.w, 0.f);
    out4[(size_t)node * 32 + lane] = acc;
}

// ---------------------------------------------------------------------------
extern "C" void kernel_launch(void* const* d_in, const int* in_sizes, int n_in,
                              void* d_out, int out_size)
{
    const float* notes = (const float*)d_in[0];
    const float* w     = (const float*)d_in[1];
    const float* b     = (const float*)d_in[2];
    const int*   esrc  = (const int*)  d_in[3];
    const int*   edst  = (const int*)  d_in[4];
    const float* ew    = (const float*)d_in[5];

    const int H = in_sizes[2];
    const int D = in_sizes[1] / H;
    const int N = in_sizes[0] / D;
    const int E = in_sizes[3];
    const int g = 2 * N - out_size / H;

    float4* out4 = (float4*)d_out;
    const int NB = (N + SCAN_BLK - 1) / SCAN_BLK;

    hist_kernel<<<592, 256>>>(esrc, E);
    scan1_kernel<<<NB, 256>>>(N);
    scan2_kernel<<<1, 256>>>(NB);
    scan3_kernel<<<(N + 255) / 256, 256>>>(N, E);
    scatter_kernel<<<592, 256>>>(esrc, edst, ew, E);

    gemm_kernel<<<(N + BM - 1) / BM, 256>>>(
        (const float4*)notes, (const float4*)w, out4, N, g);

    gather_kernel<<<(N * 32 + 255) / 256, 256>>>(
        (const float4*)b, out4, N);
}